// round 6
// baseline (speedup 1.0000x reference)
#include <cuda_runtime.h>
#include <cuda_fp16.h>
#include <cstdint>

// fp16 mma.sync attention, cp.async double-buffered, register-resident P.
// Pre-pass converts Q/K/V fp32 -> fp16 into __device__ scratch.
// Main kernel: 1 CTA = (b,h) x 128 q rows; 8 warps x 16 rows each.
// Pass A: rowsums of exp (Q frags in regs, K pipelined). Pass B: recompute S,
// write normalized scores, P kept in registers as A-fragments -> PV mma.

namespace {
constexpr int Bc = 8, Hc = 12, Sc = 1024, Dc = 64;
constexpr int QT = 128, KT = 64, NKT = Sc / KT;
constexpr long long SCORE_ELEMS = (long long)Bc * Hc * Sc * Sc;
constexpr float EC = 0.18033688011112042f;  // log2(e) / 8
constexpr int NELEM = Bc * Hc * Sc * Dc;    // 6291456
constexpr int N4 = NELEM / 4;

constexpr int OFF_Q = 0;                     // 128x64 half = 16KB
constexpr int OFF_K0 = 16384, OFF_K1 = 24576;
constexpr int OFF_V0 = 32768, OFF_V1 = 40960;
constexpr int SMEM_TOTAL = 49152;

__device__ __forceinline__ uint32_t swz(uint32_t off) { return off ^ ((off >> 3) & 0x70); }
__device__ __forceinline__ uint32_t smem_u32(const void* p) {
    uint32_t a;
    asm("{ .reg .u64 t; cvta.to.shared.u64 t, %1; cvt.u32.u64 %0, t; }" : "=r"(a) : "l"(p));
    return a;
}
__device__ __forceinline__ uint32_t h2u(__half2 h) { return *reinterpret_cast<uint32_t*>(&h); }
__device__ __forceinline__ float ex2(float x) {
    float r;
    asm("ex2.approx.f32 %0, %1;" : "=f"(r) : "f"(x));
    return r;
}
__device__ __forceinline__ void ldsm4(uint32_t r[4], uint32_t a) {
    asm volatile("ldmatrix.sync.aligned.m8n8.x4.shared.b16 {%0,%1,%2,%3}, [%4];"
                 : "=r"(r[0]), "=r"(r[1]), "=r"(r[2]), "=r"(r[3]) : "r"(a));
}
__device__ __forceinline__ void ldsm4t(uint32_t r[4], uint32_t a) {
    asm volatile("ldmatrix.sync.aligned.m8n8.x4.trans.shared.b16 {%0,%1,%2,%3}, [%4];"
                 : "=r"(r[0]), "=r"(r[1]), "=r"(r[2]), "=r"(r[3]) : "r"(a));
}
__device__ __forceinline__ void mma16816(float c[4], const uint32_t a[4],
                                         uint32_t b0, uint32_t b1) {
    asm volatile(
        "mma.sync.aligned.m16n8k16.row.col.f32.f16.f16.f32 "
        "{%0,%1,%2,%3}, {%4,%5,%6,%7}, {%8,%9}, {%0,%1,%2,%3};"
        : "+f"(c[0]), "+f"(c[1]), "+f"(c[2]), "+f"(c[3])
        : "r"(a[0]), "r"(a[1]), "r"(a[2]), "r"(a[3]), "r"(b0), "r"(b1));
}
__device__ __forceinline__ void cpa16(uint32_t d, const void* s) {
    asm volatile("cp.async.cg.shared.global [%0], [%1], 16;" :: "r"(d), "l"(s) : "memory");
}
#define CP_COMMIT() asm volatile("cp.async.commit_group;" ::: "memory")
#define CP_WAIT0()  asm volatile("cp.async.wait_group 0;" ::: "memory")
}  // namespace

__device__ __align__(16) __half g_qh[NELEM];
__device__ __align__(16) __half g_kh[NELEM];
__device__ __align__(16) __half g_vh[NELEM];

__global__ __launch_bounds__(256)
void cvt_kernel(const float4* __restrict__ q, const float4* __restrict__ k,
                const float4* __restrict__ v) {
    int i = blockIdx.x * blockDim.x + threadIdx.x;
    const float4* src;
    uint2* dst;
    int j;
    if (i < N4)          { src = q; dst = reinterpret_cast<uint2*>(g_qh); j = i; }
    else if (i < 2 * N4) { src = k; dst = reinterpret_cast<uint2*>(g_kh); j = i - N4; }
    else                 { src = v; dst = reinterpret_cast<uint2*>(g_vh); j = i - 2 * N4; }
    float4 x = src[j];
    dst[j] = make_uint2(h2u(__floats2half2_rn(x.x, x.y)), h2u(__floats2half2_rn(x.z, x.w)));
}

namespace {
// copy one 64x64 fp16 tile (8KB) into swizzled smem via cp.async (2 chunks/thread)
__device__ __forceinline__ void load_tile64(uint32_t dstBase, const __half* gsrc, int tid) {
    #pragma unroll
    for (int i = 0; i < 2; i++) {
        int c = tid + i * 256;
        int r = c >> 3, ch = c & 7;
        cpa16(dstBase + swz((uint32_t)(r * 128 + ch * 16)), gsrc + r * 64 + ch * 8);
    }
}
}  // namespace

__global__ __launch_bounds__(256, 2)
void sdpa_kernel(float* __restrict__ out) {
    extern __shared__ char smem[];
    const uint32_t sb = smem_u32(smem);
    const int tid = threadIdx.x, lane = tid & 31, wid = tid >> 5;
    const int g = lane >> 2, m = lane & 3;
    const int rs = wid * 16;                       // warp owns rows rs..rs+15
    const uint32_t xr = (uint32_t)((lane & 7) << 4);

    const int bh = blockIdx.y, qb = blockIdx.x;
    const __half* qg  = g_qh + ((long long)bh * Sc + qb * QT) * Dc;
    const __half* kgb = g_kh + (long long)bh * Sc * Dc;
    const __half* vgb = g_vh + (long long)bh * Sc * Dc;
    float* score = out + (long long)bh * Sc * Sc + (long long)(qb * QT) * Sc;
    float* ctx   = out + SCORE_ELEMS + ((long long)bh * Sc + qb * QT) * Dc;

    // ---- prologue: Q (16KB) + K tile 0 ----
    #pragma unroll
    for (int i = 0; i < 4; i++) {
        int c = tid + i * 256;
        int r = c >> 3, ch = c & 7;
        cpa16(sb + OFF_Q + swz((uint32_t)(r * 128 + ch * 16)), qg + r * 64 + ch * 8);
    }
    load_tile64(sb + OFF_K0, kgb, tid);
    CP_COMMIT();
    CP_WAIT0();
    __syncthreads();

    // Q fragments in registers, reused for all 32 QK tiles
    uint32_t qf[4][4];
    {
        uint32_t aq = sb + OFF_Q + (uint32_t)((rs + (lane & 15)) * 128);
        #pragma unroll
        for (int kk = 0; kk < 4; kk++)
            ldsm4(qf[kk], aq + (((uint32_t)(kk * 32 + ((lane >> 4) * 16))) ^ xr));
    }

    const uint32_t krow = (uint32_t)((((lane >> 4) << 3) + (lane & 7)) * 128);
    const uint32_t vrow = (uint32_t)((lane & 15) * 128);
    const uint32_t vc0 = (uint32_t)((lane >> 4) * 16);

    // =================== pass A: row sums ===================
    float rsum0 = 0.f, rsum1 = 0.f;
    for (int kt = 0; kt < NKT; kt++) {
        if (kt + 1 < NKT) {
            load_tile64(sb + (((kt + 1) & 1) ? OFF_K1 : OFF_K0),
                        kgb + (long long)(kt + 1) * KT * Dc, tid);
            CP_COMMIT();
        }
        const uint32_t kbase = sb + ((kt & 1) ? OFF_K1 : OFF_K0) + krow;
        float acc[8][4];
        #pragma unroll
        for (int nf = 0; nf < 8; nf++) acc[nf][0] = acc[nf][1] = acc[nf][2] = acc[nf][3] = 0.f;
        #pragma unroll
        for (int kk = 0; kk < 4; kk++) {
            uint32_t kb = ((uint32_t)(kk * 32 + (((lane >> 3) & 1) * 16))) ^ xr;
            #pragma unroll
            for (int nb = 0; nb < 4; nb++) {
                uint32_t B[4];
                ldsm4(B, kbase + (uint32_t)(nb * 2048) + kb);
                mma16816(acc[2 * nb],     qf[kk], B[0], B[1]);
                mma16816(acc[2 * nb + 1], qf[kk], B[2], B[3]);
            }
        }
        #pragma unroll
        for (int nf = 0; nf < 8; nf++) {
            rsum0 += ex2(acc[nf][0] * EC) + ex2(acc[nf][1] * EC);
            rsum1 += ex2(acc[nf][2] * EC) + ex2(acc[nf][3] * EC);
        }
        if (kt + 1 < NKT) { CP_WAIT0(); __syncthreads(); }
    }

    // ---- transition: issue pass-B tile 0 (K0+V0), reduce rowsums meanwhile ----
    load_tile64(sb + OFF_K0, kgb, tid);
    load_tile64(sb + OFF_V0, vgb, tid);
    CP_COMMIT();

    rsum0 += __shfl_xor_sync(0xffffffffu, rsum0, 1);
    rsum0 += __shfl_xor_sync(0xffffffffu, rsum0, 2);
    rsum1 += __shfl_xor_sync(0xffffffffu, rsum1, 1);
    rsum1 += __shfl_xor_sync(0xffffffffu, rsum1, 2);
    const float inv0 = 1.f / rsum0, inv1 = 1.f / rsum1;

    CP_WAIT0();
    __syncthreads();

    // =================== pass B: scores + context ===================
    float cc[8][4];
    #pragma unroll
    for (int nf = 0; nf < 8; nf++) cc[nf][0] = cc[nf][1] = cc[nf][2] = cc[nf][3] = 0.f;

    for (int kt = 0; kt < NKT; kt++) {
        if (kt + 1 < NKT) {
            uint32_t b = ((kt + 1) & 1) ? 1u : 0u;
            load_tile64(sb + (b ? OFF_K1 : OFF_K0), kgb + (long long)(kt + 1) * KT * Dc, tid);
            load_tile64(sb + (b ? OFF_V1 : OFF_V0), vgb + (long long)(kt + 1) * KT * Dc, tid);
            CP_COMMIT();
        }
        const uint32_t kbase = sb + ((kt & 1) ? OFF_K1 : OFF_K0) + krow;
        const uint32_t vbase = sb + ((kt & 1) ? OFF_V1 : OFF_V0) + vrow;

        float acc[8][4];
        #pragma unroll
        for (int nf = 0; nf < 8; nf++) acc[nf][0] = acc[nf][1] = acc[nf][2] = acc[nf][3] = 0.f;
        #pragma unroll
        for (int kk = 0; kk < 4; kk++) {
            uint32_t kb = ((uint32_t)(kk * 32 + (((lane >> 3) & 1) * 16))) ^ xr;
            #pragma unroll
            for (int nb = 0; nb < 4; nb++) {
                uint32_t B[4];
                ldsm4(B, kbase + (uint32_t)(nb * 2048) + kb);
                mma16816(acc[2 * nb],     qf[kk], B[0], B[1]);
                mma16816(acc[2 * nb + 1], qf[kk], B[2], B[3]);
            }
        }

        // p = exp2(s*EC)*inv, in place; write normalized scores (streaming)
        #pragma unroll
        for (int nf = 0; nf < 8; nf++) {
            acc[nf][0] = ex2(acc[nf][0] * EC) * inv0;
            acc[nf][1] = ex2(acc[nf][1] * EC) * inv0;
            acc[nf][2] = ex2(acc[nf][2] * EC) * inv1;
            acc[nf][3] = ex2(acc[nf][3] * EC) * inv1;
            int colG = kt * KT + nf * 8 + 2 * m;
            __stcs(reinterpret_cast<float2*>(score + (long long)(rs + g) * Sc + colG),
                   make_float2(acc[nf][0], acc[nf][1]));
            __stcs(reinterpret_cast<float2*>(score + (long long)(rs + 8 + g) * Sc + colG),
                   make_float2(acc[nf][2], acc[nf][3]));
        }

        // PV: P stays in registers (C-fragment == A-fragment layout)
        #pragma unroll
        for (int c = 0; c < 4; c++) {   // k chunks of 16 (seq)
            uint32_t pa[4];
            pa[0] = h2u(__floats2half2_rn(acc[2 * c][0],     acc[2 * c][1]));
            pa[1] = h2u(__floats2half2_rn(acc[2 * c][2],     acc[2 * c][3]));
            pa[2] = h2u(__floats2half2_rn(acc[2 * c + 1][0], acc[2 * c + 1][1]));
            pa[3] = h2u(__floats2half2_rn(acc[2 * c + 1][2], acc[2 * c + 1][3]));
            uint32_t vb = vbase + (uint32_t)(c * 2048);
            #pragma unroll
            for (int db = 0; db < 4; db++) {
                uint32_t B[4];
                ldsm4t(B, vb + ((vc0 + (uint32_t)(db * 32)) ^ xr));
                mma16816(cc[2 * db],     pa, B[0], B[1]);
                mma16816(cc[2 * db + 1], pa, B[2], B[3]);
            }
        }
        if (kt + 1 < NKT) { CP_WAIT0(); __syncthreads(); }
    }

    // ---- write context ----
    #pragma unroll
    for (int nf = 0; nf < 8; nf++) {
        int colG = nf * 8 + 2 * m;
        __stcs(reinterpret_cast<float2*>(ctx + (long long)(rs + g) * Dc + colG),
               make_float2(cc[nf][0], cc[nf][1]));
        __stcs(reinterpret_cast<float2*>(ctx + (long long)(rs + 8 + g) * Dc + colG),
               make_float2(cc[nf][2], cc[nf][3]));
    }
}

extern "C" void kernel_launch(void* const* d_in, const int* in_sizes, int n_in,
                              void* d_out, int out_size) {
    (void)in_sizes; (void)n_in; (void)out_size;
    const float4* q = (const float4*)d_in[0];
    const float4* k = (const float4*)d_in[1];
    const float4* v = (const float4*)d_in[2];
    float* out = (float*)d_out;

    cvt_kernel<<<(3 * N4 + 255) / 256, 256>>>(q, k, v);

    cudaFuncSetAttribute(sdpa_kernel,
                         cudaFuncAttributeMaxDynamicSharedMemorySize, SMEM_TOTAL);
    dim3 grid(Sc / QT, Bc * Hc);  // 8 x 96
    sdpa_kernel<<<grid, 256, SMEM_TOTAL>>>(out);
}

// round 7
// speedup vs baseline: 1.0028x; 1.0028x over previous
#include <cuda_runtime.h>
#include <cuda_fp16.h>
#include <cstdint>

// fp16 mma.sync attention, cp.async double-buffered, register-resident P.
// Pre-pass converts Q/K/V fp32 -> fp16 into __device__ scratch.
// Main kernel: 1 CTA = (b,h) x 128 q rows; 8 warps x 16 rows each.
// Pass A: rowsums of exp (Q frags in regs, K pipelined). Pass B: recompute S,
// write normalized scores, P kept in registers as A-fragments -> PV mma.

namespace {
constexpr int Bc = 8, Hc = 12, Sc = 1024, Dc = 64;
constexpr int QT = 128, KT = 64, NKT = Sc / KT;
constexpr long long SCORE_ELEMS = (long long)Bc * Hc * Sc * Sc;
constexpr float EC = 0.18033688011112042f;  // log2(e) / 8
constexpr int NELEM = Bc * Hc * Sc * Dc;    // 6291456
constexpr int N4 = NELEM / 4;

constexpr int OFF_Q = 0;                     // 128x64 half = 16KB
constexpr int OFF_K0 = 16384, OFF_K1 = 24576;
constexpr int OFF_V0 = 32768, OFF_V1 = 40960;
constexpr int SMEM_TOTAL = 49152;

__device__ __forceinline__ uint32_t swz(uint32_t off) { return off ^ ((off >> 3) & 0x70); }
__device__ __forceinline__ uint32_t smem_u32(const void* p) {
    uint32_t a;
    asm("{ .reg .u64 t; cvta.to.shared.u64 t, %1; cvt.u32.u64 %0, t; }" : "=r"(a) : "l"(p));
    return a;
}
__device__ __forceinline__ uint32_t h2u(__half2 h) { return *reinterpret_cast<uint32_t*>(&h); }
__device__ __forceinline__ float ex2(float x) {
    float r;
    asm("ex2.approx.f32 %0, %1;" : "=f"(r) : "f"(x));
    return r;
}
__device__ __forceinline__ void ldsm4(uint32_t r[4], uint32_t a) {
    asm volatile("ldmatrix.sync.aligned.m8n8.x4.shared.b16 {%0,%1,%2,%3}, [%4];"
                 : "=r"(r[0]), "=r"(r[1]), "=r"(r[2]), "=r"(r[3]) : "r"(a));
}
__device__ __forceinline__ void ldsm4t(uint32_t r[4], uint32_t a) {
    asm volatile("ldmatrix.sync.aligned.m8n8.x4.trans.shared.b16 {%0,%1,%2,%3}, [%4];"
                 : "=r"(r[0]), "=r"(r[1]), "=r"(r[2]), "=r"(r[3]) : "r"(a));
}
__device__ __forceinline__ void mma16816(float c[4], const uint32_t a[4],
                                         uint32_t b0, uint32_t b1) {
    asm volatile(
        "mma.sync.aligned.m16n8k16.row.col.f32.f16.f16.f32 "
        "{%0,%1,%2,%3}, {%4,%5,%6,%7}, {%8,%9}, {%0,%1,%2,%3};"
        : "+f"(c[0]), "+f"(c[1]), "+f"(c[2]), "+f"(c[3])
        : "r"(a[0]), "r"(a[1]), "r"(a[2]), "r"(a[3]), "r"(b0), "r"(b1));
}
__device__ __forceinline__ void cpa16(uint32_t d, const void* s) {
    asm volatile("cp.async.cg.shared.global [%0], [%1], 16;" :: "r"(d), "l"(s) : "memory");
}
#define CP_COMMIT() asm volatile("cp.async.commit_group;" ::: "memory")
#define CP_WAIT0()  asm volatile("cp.async.wait_group 0;" ::: "memory")
}  // namespace

__device__ __align__(16) __half g_qh[NELEM];
__device__ __align__(16) __half g_kh[NELEM];
__device__ __align__(16) __half g_vh[NELEM];

__global__ __launch_bounds__(256)
void cvt_kernel(const float4* __restrict__ q, const float4* __restrict__ k,
                const float4* __restrict__ v) {
    int i = blockIdx.x * blockDim.x + threadIdx.x;
    const float4* src;
    uint2* dst;
    int j;
    if (i < N4)          { src = q; dst = reinterpret_cast<uint2*>(g_qh); j = i; }
    else if (i < 2 * N4) { src = k; dst = reinterpret_cast<uint2*>(g_kh); j = i - N4; }
    else                 { src = v; dst = reinterpret_cast<uint2*>(g_vh); j = i - 2 * N4; }
    float4 x = src[j];
    dst[j] = make_uint2(h2u(__floats2half2_rn(x.x, x.y)), h2u(__floats2half2_rn(x.z, x.w)));
}

namespace {
// copy one 64x64 fp16 tile (8KB) into swizzled smem via cp.async (2 chunks/thread)
__device__ __forceinline__ void load_tile64(uint32_t dstBase, const __half* gsrc, int tid) {
    #pragma unroll
    for (int i = 0; i < 2; i++) {
        int c = tid + i * 256;
        int r = c >> 3, ch = c & 7;
        cpa16(dstBase + swz((uint32_t)(r * 128 + ch * 16)), gsrc + r * 64 + ch * 8);
    }
}
}  // namespace

__global__ __launch_bounds__(256, 2)
void sdpa_kernel(float* __restrict__ out) {
    extern __shared__ char smem[];
    const uint32_t sb = smem_u32(smem);
    const int tid = threadIdx.x, lane = tid & 31, wid = tid >> 5;
    const int g = lane >> 2, m = lane & 3;
    const int rs = wid * 16;                       // warp owns rows rs..rs+15
    const uint32_t xr = (uint32_t)((lane & 7) << 4);

    const int bh = blockIdx.y, qb = blockIdx.x;
    const __half* qg  = g_qh + ((long long)bh * Sc + qb * QT) * Dc;
    const __half* kgb = g_kh + (long long)bh * Sc * Dc;
    const __half* vgb = g_vh + (long long)bh * Sc * Dc;
    float* score = out + (long long)bh * Sc * Sc + (long long)(qb * QT) * Sc;
    float* ctx   = out + SCORE_ELEMS + ((long long)bh * Sc + qb * QT) * Dc;

    // ---- prologue: Q (16KB) + K tile 0 ----
    #pragma unroll
    for (int i = 0; i < 4; i++) {
        int c = tid + i * 256;
        int r = c >> 3, ch = c & 7;
        cpa16(sb + OFF_Q + swz((uint32_t)(r * 128 + ch * 16)), qg + r * 64 + ch * 8);
    }
    load_tile64(sb + OFF_K0, kgb, tid);
    CP_COMMIT();
    CP_WAIT0();
    __syncthreads();

    // Q fragments in registers, reused for all 32 QK tiles
    uint32_t qf[4][4];
    {
        uint32_t aq = sb + OFF_Q + (uint32_t)((rs + (lane & 15)) * 128);
        #pragma unroll
        for (int kk = 0; kk < 4; kk++)
            ldsm4(qf[kk], aq + (((uint32_t)(kk * 32 + ((lane >> 4) * 16))) ^ xr));
    }

    const uint32_t krow = (uint32_t)((((lane >> 4) << 3) + (lane & 7)) * 128);
    const uint32_t vrow = (uint32_t)((lane & 15) * 128);
    const uint32_t vc0 = (uint32_t)((lane >> 4) * 16);

    // =================== pass A: row sums ===================
    float rsum0 = 0.f, rsum1 = 0.f;
    for (int kt = 0; kt < NKT; kt++) {
        if (kt + 1 < NKT) {
            load_tile64(sb + (((kt + 1) & 1) ? OFF_K1 : OFF_K0),
                        kgb + (long long)(kt + 1) * KT * Dc, tid);
            CP_COMMIT();
        }
        const uint32_t kbase = sb + ((kt & 1) ? OFF_K1 : OFF_K0) + krow;
        float acc[8][4];
        #pragma unroll
        for (int nf = 0; nf < 8; nf++) acc[nf][0] = acc[nf][1] = acc[nf][2] = acc[nf][3] = 0.f;
        #pragma unroll
        for (int kk = 0; kk < 4; kk++) {
            uint32_t kb = ((uint32_t)(kk * 32 + (((lane >> 3) & 1) * 16))) ^ xr;
            #pragma unroll
            for (int nb = 0; nb < 4; nb++) {
                uint32_t B[4];
                ldsm4(B, kbase + (uint32_t)(nb * 2048) + kb);
                mma16816(acc[2 * nb],     qf[kk], B[0], B[1]);
                mma16816(acc[2 * nb + 1], qf[kk], B[2], B[3]);
            }
        }
        #pragma unroll
        for (int nf = 0; nf < 8; nf++) {
            rsum0 += ex2(acc[nf][0] * EC) + ex2(acc[nf][1] * EC);
            rsum1 += ex2(acc[nf][2] * EC) + ex2(acc[nf][3] * EC);
        }
        if (kt + 1 < NKT) { CP_WAIT0(); __syncthreads(); }
    }

    // ---- transition: issue pass-B tile 0 (K0+V0), reduce rowsums meanwhile ----
    load_tile64(sb + OFF_K0, kgb, tid);
    load_tile64(sb + OFF_V0, vgb, tid);
    CP_COMMIT();

    rsum0 += __shfl_xor_sync(0xffffffffu, rsum0, 1);
    rsum0 += __shfl_xor_sync(0xffffffffu, rsum0, 2);
    rsum1 += __shfl_xor_sync(0xffffffffu, rsum1, 1);
    rsum1 += __shfl_xor_sync(0xffffffffu, rsum1, 2);
    const float inv0 = 1.f / rsum0, inv1 = 1.f / rsum1;

    CP_WAIT0();
    __syncthreads();

    // =================== pass B: scores + context ===================
    float cc[8][4];
    #pragma unroll
    for (int nf = 0; nf < 8; nf++) cc[nf][0] = cc[nf][1] = cc[nf][2] = cc[nf][3] = 0.f;

    for (int kt = 0; kt < NKT; kt++) {
        if (kt + 1 < NKT) {
            uint32_t b = ((kt + 1) & 1) ? 1u : 0u;
            load_tile64(sb + (b ? OFF_K1 : OFF_K0), kgb + (long long)(kt + 1) * KT * Dc, tid);
            load_tile64(sb + (b ? OFF_V1 : OFF_V0), vgb + (long long)(kt + 1) * KT * Dc, tid);
            CP_COMMIT();
        }
        const uint32_t kbase = sb + ((kt & 1) ? OFF_K1 : OFF_K0) + krow;
        const uint32_t vbase = sb + ((kt & 1) ? OFF_V1 : OFF_V0) + vrow;

        float acc[8][4];
        #pragma unroll
        for (int nf = 0; nf < 8; nf++) acc[nf][0] = acc[nf][1] = acc[nf][2] = acc[nf][3] = 0.f;
        #pragma unroll
        for (int kk = 0; kk < 4; kk++) {
            uint32_t kb = ((uint32_t)(kk * 32 + (((lane >> 3) & 1) * 16))) ^ xr;
            #pragma unroll
            for (int nb = 0; nb < 4; nb++) {
                uint32_t B[4];
                ldsm4(B, kbase + (uint32_t)(nb * 2048) + kb);
                mma16816(acc[2 * nb],     qf[kk], B[0], B[1]);
                mma16816(acc[2 * nb + 1], qf[kk], B[2], B[3]);
            }
        }

        // p = exp2(s*EC)*inv, in place; write normalized scores (streaming)
        #pragma unroll
        for (int nf = 0; nf < 8; nf++) {
            acc[nf][0] = ex2(acc[nf][0] * EC) * inv0;
            acc[nf][1] = ex2(acc[nf][1] * EC) * inv0;
            acc[nf][2] = ex2(acc[nf][2] * EC) * inv1;
            acc[nf][3] = ex2(acc[nf][3] * EC) * inv1;
            int colG = kt * KT + nf * 8 + 2 * m;
            __stcs(reinterpret_cast<float2*>(score + (long long)(rs + g) * Sc + colG),
                   make_float2(acc[nf][0], acc[nf][1]));
            __stcs(reinterpret_cast<float2*>(score + (long long)(rs + 8 + g) * Sc + colG),
                   make_float2(acc[nf][2], acc[nf][3]));
        }

        // PV: P stays in registers (C-fragment == A-fragment layout)
        #pragma unroll
        for (int c = 0; c < 4; c++) {   // k chunks of 16 (seq)
            uint32_t pa[4];
            pa[0] = h2u(__floats2half2_rn(acc[2 * c][0],     acc[2 * c][1]));
            pa[1] = h2u(__floats2half2_rn(acc[2 * c][2],     acc[2 * c][3]));
            pa[2] = h2u(__floats2half2_rn(acc[2 * c + 1][0], acc[2 * c + 1][1]));
            pa[3] = h2u(__floats2half2_rn(acc[2 * c + 1][2], acc[2 * c + 1][3]));
            uint32_t vb = vbase + (uint32_t)(c * 2048);
            #pragma unroll
            for (int db = 0; db < 4; db++) {
                uint32_t B[4];
                ldsm4t(B, vb + ((vc0 + (uint32_t)(db * 32)) ^ xr));
                mma16816(cc[2 * db],     pa, B[0], B[1]);
                mma16816(cc[2 * db + 1], pa, B[2], B[3]);
            }
        }
        if (kt + 1 < NKT) { CP_WAIT0(); __syncthreads(); }
    }

    // ---- write context ----
    #pragma unroll
    for (int nf = 0; nf < 8; nf++) {
        int colG = nf * 8 + 2 * m;
        __stcs(reinterpret_cast<float2*>(ctx + (long long)(rs + g) * Dc + colG),
               make_float2(cc[nf][0], cc[nf][1]));
        __stcs(reinterpret_cast<float2*>(ctx + (long long)(rs + 8 + g) * Dc + colG),
               make_float2(cc[nf][2], cc[nf][3]));
    }
}

extern "C" void kernel_launch(void* const* d_in, const int* in_sizes, int n_in,
                              void* d_out, int out_size) {
    (void)in_sizes; (void)n_in; (void)out_size;
    const float4* q = (const float4*)d_in[0];
    const float4* k = (const float4*)d_in[1];
    const float4* v = (const float4*)d_in[2];
    float* out = (float*)d_out;

    cvt_kernel<<<(3 * N4 + 255) / 256, 256>>>(q, k, v);

    cudaFuncSetAttribute(sdpa_kernel,
                         cudaFuncAttributeMaxDynamicSharedMemorySize, SMEM_TOTAL);
    dim3 grid(Sc / QT, Bc * Hc);  // 8 x 96
    sdpa_kernel<<<grid, 256, SMEM_TOTAL>>>(out);
}

// round 8
// speedup vs baseline: 1.1046x; 1.1015x over previous
#include <cuda_runtime.h>
#include <cuda_fp16.h>
#include <cstdint>

// fp16 mma.sync attention. 128 threads/CTA, 4 warps x 32 q-rows: each warp
// holds 2 m16 A-fragments so every K/V B-fragment ldmatrix feeds 2 mmas
// (halves L1 ldsm traffic vs 8x16-row warps). cp.async double buffering,
// register-resident P, fp16 pre-converted Q/K/V in __device__ scratch.

namespace {
constexpr int Bc = 8, Hc = 12, Sc = 1024, Dc = 64;
constexpr int QT = 128, KT = 64, NKT = Sc / KT;
constexpr long long SCORE_ELEMS = (long long)Bc * Hc * Sc * Sc;
constexpr float EC = 0.18033688011112042f;  // log2(e) / 8
constexpr int NELEM = Bc * Hc * Sc * Dc;
constexpr int N4 = NELEM / 4;
constexpr int NT = 128;                      // threads per CTA

constexpr int OFF_Q = 0;                     // 128x64 half = 16KB
constexpr int OFF_K0 = 16384, OFF_K1 = 24576;
constexpr int OFF_V0 = 32768, OFF_V1 = 40960;
constexpr int SMEM_TOTAL = 49152;

__device__ __forceinline__ uint32_t swz(uint32_t off) { return off ^ ((off >> 3) & 0x70); }
__device__ __forceinline__ uint32_t smem_u32(const void* p) {
    uint32_t a;
    asm("{ .reg .u64 t; cvta.to.shared.u64 t, %1; cvt.u32.u64 %0, t; }" : "=r"(a) : "l"(p));
    return a;
}
__device__ __forceinline__ uint32_t h2u(__half2 h) { return *reinterpret_cast<uint32_t*>(&h); }
__device__ __forceinline__ float ex2(float x) {
    float r;
    asm("ex2.approx.f32 %0, %1;" : "=f"(r) : "f"(x));
    return r;
}
__device__ __forceinline__ void ldsm4(uint32_t r[4], uint32_t a) {
    asm volatile("ldmatrix.sync.aligned.m8n8.x4.shared.b16 {%0,%1,%2,%3}, [%4];"
                 : "=r"(r[0]), "=r"(r[1]), "=r"(r[2]), "=r"(r[3]) : "r"(a));
}
__device__ __forceinline__ void ldsm4t(uint32_t r[4], uint32_t a) {
    asm volatile("ldmatrix.sync.aligned.m8n8.x4.trans.shared.b16 {%0,%1,%2,%3}, [%4];"
                 : "=r"(r[0]), "=r"(r[1]), "=r"(r[2]), "=r"(r[3]) : "r"(a));
}
__device__ __forceinline__ void mma16816(float c[4], const uint32_t a[4],
                                         uint32_t b0, uint32_t b1) {
    asm volatile(
        "mma.sync.aligned.m16n8k16.row.col.f32.f16.f16.f32 "
        "{%0,%1,%2,%3}, {%4,%5,%6,%7}, {%8,%9}, {%0,%1,%2,%3};"
        : "+f"(c[0]), "+f"(c[1]), "+f"(c[2]), "+f"(c[3])
        : "r"(a[0]), "r"(a[1]), "r"(a[2]), "r"(a[3]), "r"(b0), "r"(b1));
}
__device__ __forceinline__ void cpa16(uint32_t d, const void* s) {
    asm volatile("cp.async.cg.shared.global [%0], [%1], 16;" :: "r"(d), "l"(s) : "memory");
}
#define CP_COMMIT() asm volatile("cp.async.commit_group;" ::: "memory")
#define CP_WAIT0()  asm volatile("cp.async.wait_group 0;" ::: "memory")
}  // namespace

__device__ __align__(16) __half g_qh[NELEM];
__device__ __align__(16) __half g_kh[NELEM];
__device__ __align__(16) __half g_vh[NELEM];

__global__ __launch_bounds__(256)
void cvt_kernel(const float4* __restrict__ q, const float4* __restrict__ k,
                const float4* __restrict__ v) {
    int i = blockIdx.x * blockDim.x + threadIdx.x;
    const float4* src;
    uint2* dst;
    int j;
    if (i < N4)          { src = q; dst = reinterpret_cast<uint2*>(g_qh); j = i; }
    else if (i < 2 * N4) { src = k; dst = reinterpret_cast<uint2*>(g_kh); j = i - N4; }
    else                 { src = v; dst = reinterpret_cast<uint2*>(g_vh); j = i - 2 * N4; }
    float4 x = src[j];
    dst[j] = make_uint2(h2u(__floats2half2_rn(x.x, x.y)), h2u(__floats2half2_rn(x.z, x.w)));
}

namespace {
// 64x64 fp16 tile (8KB = 512 x 16B chunks) via cp.async; 4 chunks/thread @128thr
__device__ __forceinline__ void load_tile64(uint32_t dstBase, const __half* gsrc, int tid) {
    #pragma unroll
    for (int i = 0; i < 4; i++) {
        int c = tid + i * NT;
        int r = c >> 3, ch = c & 7;
        cpa16(dstBase + swz((uint32_t)(r * 128 + ch * 16)), gsrc + r * 64 + ch * 8);
    }
}
}  // namespace

__global__ __launch_bounds__(NT, 2)
void sdpa_kernel(float* __restrict__ out) {
    extern __shared__ char smem[];
    const uint32_t sb = smem_u32(smem);
    const int tid = threadIdx.x, lane = tid & 31, wid = tid >> 5;
    const int g = lane >> 2, m = lane & 3;
    const int rs = wid * 32;                       // warp owns 32 rows
    const uint32_t xr = (uint32_t)((lane & 7) << 4);

    const int bh = blockIdx.y, qb = blockIdx.x;
    const __half* qg  = g_qh + ((long long)bh * Sc + qb * QT) * Dc;
    const __half* kgb = g_kh + (long long)bh * Sc * Dc;
    const __half* vgb = g_vh + (long long)bh * Sc * Dc;
    float* score = out + (long long)bh * Sc * Sc + (long long)(qb * QT) * Sc;
    float* ctx   = out + SCORE_ELEMS + ((long long)bh * Sc + qb * QT) * Dc;

    // ---- prologue: Q (16KB) + K tile 0 ----
    #pragma unroll
    for (int i = 0; i < 8; i++) {
        int c = tid + i * NT;
        int r = c >> 3, ch = c & 7;
        cpa16(sb + OFF_Q + swz((uint32_t)(r * 128 + ch * 16)), qg + r * 64 + ch * 8);
    }
    load_tile64(sb + OFF_K0, kgb, tid);
    CP_COMMIT();
    CP_WAIT0();
    __syncthreads();

    // Q fragments in registers: 2 m16 frags x 4 k-chunks
    uint32_t qf[4][2][4];
    #pragma unroll
    for (int mf = 0; mf < 2; mf++) {
        uint32_t aq = sb + OFF_Q + (uint32_t)((rs + mf * 16 + (lane & 15)) * 128);
        #pragma unroll
        for (int kk = 0; kk < 4; kk++)
            ldsm4(qf[kk][mf], aq + (((uint32_t)(kk * 32 + ((lane >> 4) * 16))) ^ xr));
    }

    const uint32_t krow = (uint32_t)((((lane >> 4) << 3) + (lane & 7)) * 128);
    const uint32_t vrow = (uint32_t)((lane & 15) * 128);
    const uint32_t vc0 = (uint32_t)((lane >> 4) * 16);

    // =================== pass A: row sums ===================
    float rsum[2][2] = {{0.f, 0.f}, {0.f, 0.f}};
    for (int kt = 0; kt < NKT; kt++) {
        if (kt + 1 < NKT) {
            load_tile64(sb + (((kt + 1) & 1) ? OFF_K1 : OFF_K0),
                        kgb + (long long)(kt + 1) * KT * Dc, tid);
            CP_COMMIT();
        }
        const uint32_t kbase = sb + ((kt & 1) ? OFF_K1 : OFF_K0) + krow;
        float acc[2][8][4];
        #pragma unroll
        for (int mf = 0; mf < 2; mf++)
            #pragma unroll
            for (int nf = 0; nf < 8; nf++)
                acc[mf][nf][0] = acc[mf][nf][1] = acc[mf][nf][2] = acc[mf][nf][3] = 0.f;
        #pragma unroll
        for (int kk = 0; kk < 4; kk++) {
            uint32_t kb = ((uint32_t)(kk * 32 + (((lane >> 3) & 1) * 16))) ^ xr;
            #pragma unroll
            for (int nb = 0; nb < 4; nb++) {
                uint32_t B[4];
                ldsm4(B, kbase + (uint32_t)(nb * 2048) + kb);
                #pragma unroll
                for (int mf = 0; mf < 2; mf++) {
                    mma16816(acc[mf][2 * nb],     qf[kk][mf], B[0], B[1]);
                    mma16816(acc[mf][2 * nb + 1], qf[kk][mf], B[2], B[3]);
                }
            }
        }
        #pragma unroll
        for (int mf = 0; mf < 2; mf++)
            #pragma unroll
            for (int nf = 0; nf < 8; nf++) {
                rsum[mf][0] += ex2(acc[mf][nf][0] * EC) + ex2(acc[mf][nf][1] * EC);
                rsum[mf][1] += ex2(acc[mf][nf][2] * EC) + ex2(acc[mf][nf][3] * EC);
            }
        if (kt + 1 < NKT) { CP_WAIT0(); __syncthreads(); }
    }

    // ---- transition: issue pass-B tile 0 while reducing ----
    load_tile64(sb + OFF_K0, kgb, tid);
    load_tile64(sb + OFF_V0, vgb, tid);
    CP_COMMIT();

    float inv[2][2];
    #pragma unroll
    for (int mf = 0; mf < 2; mf++)
        #pragma unroll
        for (int h = 0; h < 2; h++) {
            float s = rsum[mf][h];
            s += __shfl_xor_sync(0xffffffffu, s, 1);
            s += __shfl_xor_sync(0xffffffffu, s, 2);
            inv[mf][h] = 1.f / s;
        }

    CP_WAIT0();
    __syncthreads();

    // =================== pass B: scores + context ===================
    float cc[2][8][4];
    #pragma unroll
    for (int mf = 0; mf < 2; mf++)
        #pragma unroll
        for (int nf = 0; nf < 8; nf++)
            cc[mf][nf][0] = cc[mf][nf][1] = cc[mf][nf][2] = cc[mf][nf][3] = 0.f;

    for (int kt = 0; kt < NKT; kt++) {
        if (kt + 1 < NKT) {
            uint32_t b = ((kt + 1) & 1) ? 1u : 0u;
            load_tile64(sb + (b ? OFF_K1 : OFF_K0), kgb + (long long)(kt + 1) * KT * Dc, tid);
            load_tile64(sb + (b ? OFF_V1 : OFF_V0), vgb + (long long)(kt + 1) * KT * Dc, tid);
            CP_COMMIT();
        }
        const uint32_t kbase = sb + ((kt & 1) ? OFF_K1 : OFF_K0) + krow;
        const uint32_t vbase = sb + ((kt & 1) ? OFF_V1 : OFF_V0) + vrow;

        float acc[2][8][4];
        #pragma unroll
        for (int mf = 0; mf < 2; mf++)
            #pragma unroll
            for (int nf = 0; nf < 8; nf++)
                acc[mf][nf][0] = acc[mf][nf][1] = acc[mf][nf][2] = acc[mf][nf][3] = 0.f;
        #pragma unroll
        for (int kk = 0; kk < 4; kk++) {
            uint32_t kb = ((uint32_t)(kk * 32 + (((lane >> 3) & 1) * 16))) ^ xr;
            #pragma unroll
            for (int nb = 0; nb < 4; nb++) {
                uint32_t B[4];
                ldsm4(B, kbase + (uint32_t)(nb * 2048) + kb);
                #pragma unroll
                for (int mf = 0; mf < 2; mf++) {
                    mma16816(acc[mf][2 * nb],     qf[kk][mf], B[0], B[1]);
                    mma16816(acc[mf][2 * nb + 1], qf[kk][mf], B[2], B[3]);
                }
            }
        }

        // p = exp2(s*EC)*inv in place; stream normalized scores
        #pragma unroll
        for (int mf = 0; mf < 2; mf++) {
            const int r0 = rs + mf * 16 + g, r1 = r0 + 8;
            #pragma unroll
            for (int nf = 0; nf < 8; nf++) {
                acc[mf][nf][0] = ex2(acc[mf][nf][0] * EC) * inv[mf][0];
                acc[mf][nf][1] = ex2(acc[mf][nf][1] * EC) * inv[mf][0];
                acc[mf][nf][2] = ex2(acc[mf][nf][2] * EC) * inv[mf][1];
                acc[mf][nf][3] = ex2(acc[mf][nf][3] * EC) * inv[mf][1];
                int colG = kt * KT + nf * 8 + 2 * m;
                __stcs(reinterpret_cast<float2*>(score + (long long)r0 * Sc + colG),
                       make_float2(acc[mf][nf][0], acc[mf][nf][1]));
                __stcs(reinterpret_cast<float2*>(score + (long long)r1 * Sc + colG),
                       make_float2(acc[mf][nf][2], acc[mf][nf][3]));
            }
        }

        // PV: P in registers; each V B-fragment feeds both m16 frags
        #pragma unroll
        for (int c = 0; c < 4; c++) {
            uint32_t pa[2][4];
            #pragma unroll
            for (int mf = 0; mf < 2; mf++) {
                pa[mf][0] = h2u(__floats2half2_rn(acc[mf][2 * c][0],     acc[mf][2 * c][1]));
                pa[mf][1] = h2u(__floats2half2_rn(acc[mf][2 * c][2],     acc[mf][2 * c][3]));
                pa[mf][2] = h2u(__floats2half2_rn(acc[mf][2 * c + 1][0], acc[mf][2 * c + 1][1]));
                pa[mf][3] = h2u(__floats2half2_rn(acc[mf][2 * c + 1][2], acc[mf][2 * c + 1][3]));
            }
            uint32_t vb = vbase + (uint32_t)(c * 2048);
            #pragma unroll
            for (int db = 0; db < 4; db++) {
                uint32_t B[4];
                ldsm4t(B, vb + ((vc0 + (uint32_t)(db * 32)) ^ xr));
                #pragma unroll
                for (int mf = 0; mf < 2; mf++) {
                    mma16816(cc[mf][2 * db],     pa[mf], B[0], B[1]);
                    mma16816(cc[mf][2 * db + 1], pa[mf], B[2], B[3]);
                }
            }
        }
        if (kt + 1 < NKT) { CP_WAIT0(); __syncthreads(); }
    }

    // ---- write context ----
    #pragma unroll
    for (int mf = 0; mf < 2; mf++) {
        const int r0 = rs + mf * 16 + g, r1 = r0 + 8;
        #pragma unroll
        for (int nf = 0; nf < 8; nf++) {
            int colG = nf * 8 + 2 * m;
            __stcs(reinterpret_cast<float2*>(ctx + (long long)r0 * Dc + colG),
                   make_float2(cc[mf][nf][0], cc[mf][nf][1]));
            __stcs(reinterpret_cast<float2*>(ctx + (long long)r1 * Dc + colG),
                   make_float2(cc[mf][nf][2], cc[mf][nf][3]));
        }
    }
}

extern "C" void kernel_launch(void* const* d_in, const int* in_sizes, int n_in,
                              void* d_out, int out_size) {
    (void)in_sizes; (void)n_in; (void)out_size;
    const float4* q = (const float4*)d_in[0];
    const float4* k = (const float4*)d_in[1];
    const float4* v = (const float4*)d_in[2];
    float* out = (float*)d_out;

    cvt_kernel<<<(3 * N4 + 255) / 256, 256>>>(q, k, v);

    cudaFuncSetAttribute(sdpa_kernel,
                         cudaFuncAttributeMaxDynamicSharedMemorySize, SMEM_TOTAL);
    dim3 grid(Sc / QT, Bc * Hc);  // 8 x 96
    sdpa_kernel<<<grid, NT, SMEM_TOTAL>>>(out);
}

// round 9
// speedup vs baseline: 1.1192x; 1.0132x over previous
#include <cuda_runtime.h>
#include <cuda_fp16.h>
#include <cstdint>

// fp16 mma.sync attention. 128 thr/CTA, 4 warps x 32 q-rows, 3 CTAs/SM.
// Chunk-wise epilogue (16 S-cols at a time) keeps live regs ~160.
// Triple-buffered K+V stages via cp.async, wait_group 1 (one tile in flight).
// Register-resident P; fp16 pre-converted Q/K/V in __device__ scratch.

namespace {
constexpr int Bc = 8, Hc = 12, Sc = 1024, Dc = 64;
constexpr int QT = 128, KT = 64, NKT = Sc / KT;
constexpr long long SCORE_ELEMS = (long long)Bc * Hc * Sc * Sc;
constexpr float EC = 0.18033688011112042f;  // log2(e) / 8
constexpr int NELEM = Bc * Hc * Sc * Dc;
constexpr int N4 = NELEM / 4;
constexpr int NT = 128;

constexpr int OFF_Q = 0;                       // 128x64 half = 16KB
constexpr int OFF_ST = 16384;                  // 3 stages x (K 8KB + V 8KB)
constexpr int STAGE_SZ = 16384, V_IN_STAGE = 8192;
constexpr int SMEM_TOTAL = OFF_ST + 3 * STAGE_SZ;  // 65536

__device__ __forceinline__ uint32_t swz(uint32_t off) { return off ^ ((off >> 3) & 0x70); }
__device__ __forceinline__ uint32_t smem_u32(const void* p) {
    uint32_t a;
    asm("{ .reg .u64 t; cvta.to.shared.u64 t, %1; cvt.u32.u64 %0, t; }" : "=r"(a) : "l"(p));
    return a;
}
__device__ __forceinline__ uint32_t h2u(__half2 h) { return *reinterpret_cast<uint32_t*>(&h); }
__device__ __forceinline__ float ex2(float x) {
    float r;
    asm("ex2.approx.f32 %0, %1;" : "=f"(r) : "f"(x));
    return r;
}
__device__ __forceinline__ void ldsm4(uint32_t r[4], uint32_t a) {
    asm volatile("ldmatrix.sync.aligned.m8n8.x4.shared.b16 {%0,%1,%2,%3}, [%4];"
                 : "=r"(r[0]), "=r"(r[1]), "=r"(r[2]), "=r"(r[3]) : "r"(a));
}
__device__ __forceinline__ void ldsm4t(uint32_t r[4], uint32_t a) {
    asm volatile("ldmatrix.sync.aligned.m8n8.x4.trans.shared.b16 {%0,%1,%2,%3}, [%4];"
                 : "=r"(r[0]), "=r"(r[1]), "=r"(r[2]), "=r"(r[3]) : "r"(a));
}
__device__ __forceinline__ void mma16816(float c[4], const uint32_t a[4],
                                         uint32_t b0, uint32_t b1) {
    asm volatile(
        "mma.sync.aligned.m16n8k16.row.col.f32.f16.f16.f32 "
        "{%0,%1,%2,%3}, {%4,%5,%6,%7}, {%8,%9}, {%0,%1,%2,%3};"
        : "+f"(c[0]), "+f"(c[1]), "+f"(c[2]), "+f"(c[3])
        : "r"(a[0]), "r"(a[1]), "r"(a[2]), "r"(a[3]), "r"(b0), "r"(b1));
}
__device__ __forceinline__ void cpa16(uint32_t d, const void* s) {
    asm volatile("cp.async.cg.shared.global [%0], [%1], 16;" :: "r"(d), "l"(s) : "memory");
}
#define CP_COMMIT() asm volatile("cp.async.commit_group;" ::: "memory")
#define CP_WAIT1()  asm volatile("cp.async.wait_group 1;" ::: "memory")
}  // namespace

__device__ __align__(16) __half g_qh[NELEM];
__device__ __align__(16) __half g_kh[NELEM];
__device__ __align__(16) __half g_vh[NELEM];

__global__ __launch_bounds__(256)
void cvt_kernel(const float4* __restrict__ q, const float4* __restrict__ k,
                const float4* __restrict__ v) {
    int i = blockIdx.x * blockDim.x + threadIdx.x;
    const float4* src;
    uint2* dst;
    int j;
    if (i < N4)          { src = q; dst = reinterpret_cast<uint2*>(g_qh); j = i; }
    else if (i < 2 * N4) { src = k; dst = reinterpret_cast<uint2*>(g_kh); j = i - N4; }
    else                 { src = v; dst = reinterpret_cast<uint2*>(g_vh); j = i - 2 * N4; }
    float4 x = src[j];
    dst[j] = make_uint2(h2u(__floats2half2_rn(x.x, x.y)), h2u(__floats2half2_rn(x.z, x.w)));
}

namespace {
// 64x64 fp16 tile (8KB = 512 x 16B chunks); 4 chunks/thread @128thr
__device__ __forceinline__ void load_tile64(uint32_t dstBase, const __half* gsrc, int tid) {
    #pragma unroll
    for (int i = 0; i < 4; i++) {
        int c = tid + i * NT;
        int r = c >> 3, ch = c & 7;
        cpa16(dstBase + swz((uint32_t)(r * 128 + ch * 16)), gsrc + r * 64 + ch * 8);
    }
}
__device__ __forceinline__ uint32_t stage_off(int kt) {
    return (uint32_t)(OFF_ST + (kt % 3) * STAGE_SZ);
}
}  // namespace

__global__ __launch_bounds__(NT, 3)
void sdpa_kernel(float* __restrict__ out) {
    extern __shared__ char smem[];
    const uint32_t sb = smem_u32(smem);
    const int tid = threadIdx.x, lane = tid & 31, wid = tid >> 5;
    const int g = lane >> 2, m = lane & 3;
    const int rs = wid * 32;
    const uint32_t xr = (uint32_t)((lane & 7) << 4);

    const int bh = blockIdx.y, qb = blockIdx.x;
    const __half* qg  = g_qh + ((long long)bh * Sc + qb * QT) * Dc;
    const __half* kgb = g_kh + (long long)bh * Sc * Dc;
    const __half* vgb = g_vh + (long long)bh * Sc * Dc;
    float* score = out + (long long)bh * Sc * Sc + (long long)(qb * QT) * Sc;
    float* ctx   = out + SCORE_ELEMS + ((long long)bh * Sc + qb * QT) * Dc;

    // ---- prologue: G0 = Q + K(0); G1 = K(1) ----
    #pragma unroll
    for (int i = 0; i < 8; i++) {
        int c = tid + i * NT;
        int r = c >> 3, ch = c & 7;
        cpa16(sb + OFF_Q + swz((uint32_t)(r * 128 + ch * 16)), qg + r * 64 + ch * 8);
    }
    load_tile64(sb + stage_off(0), kgb, tid);
    CP_COMMIT();
    load_tile64(sb + stage_off(1), kgb + (long long)KT * Dc, tid);
    CP_COMMIT();
    CP_WAIT1();           // G0 (Q + K0) landed
    __syncthreads();

    // Q fragments in registers: [kk][mf][4]
    uint32_t qf[4][2][4];
    #pragma unroll
    for (int mf = 0; mf < 2; mf++) {
        uint32_t aq = sb + OFF_Q + (uint32_t)((rs + mf * 16 + (lane & 15)) * 128);
        #pragma unroll
        for (int kk = 0; kk < 4; kk++)
            ldsm4(qf[kk][mf], aq + (((uint32_t)(kk * 32 + ((lane >> 4) * 16))) ^ xr));
    }

    const uint32_t krow = (uint32_t)((((lane >> 4) << 3) + (lane & 7)) * 128);
    const uint32_t vrow = (uint32_t)((lane & 15) * 128);
    const uint32_t vc0 = (uint32_t)((lane >> 4) * 16);
    const uint32_t kfr = (uint32_t)(((lane >> 3) & 1) * 16);

    // =================== pass A: row sums ===================
    float rsum[2][2] = {{0.f, 0.f}, {0.f, 0.f}};
    for (int kt = 0; kt < NKT; kt++) {
        CP_WAIT1();        // tile kt landed (kt+1 may be in flight)
        __syncthreads();   // also: all warps done reading stage (kt+2)%3
        if (kt + 2 < NKT)
            load_tile64(sb + stage_off(kt + 2), kgb + (long long)(kt + 2) * KT * Dc, tid);
        CP_COMMIT();       // always commit (uniform group count)

        const uint32_t kbase = sb + stage_off(kt) + krow;
        #pragma unroll
        for (int nb = 0; nb < 4; nb++) {
            float acc[2][2][4];
            #pragma unroll
            for (int mf = 0; mf < 2; mf++)
                #pragma unroll
                for (int j = 0; j < 2; j++)
                    acc[mf][j][0] = acc[mf][j][1] = acc[mf][j][2] = acc[mf][j][3] = 0.f;
            #pragma unroll
            for (int kk = 0; kk < 4; kk++) {
                uint32_t B[4];
                ldsm4(B, kbase + (uint32_t)(nb * 2048) + (((uint32_t)(kk * 32) + kfr) ^ xr));
                #pragma unroll
                for (int mf = 0; mf < 2; mf++) {
                    mma16816(acc[mf][0], qf[kk][mf], B[0], B[1]);
                    mma16816(acc[mf][1], qf[kk][mf], B[2], B[3]);
                }
            }
            #pragma unroll
            for (int mf = 0; mf < 2; mf++)
                #pragma unroll
                for (int j = 0; j < 2; j++) {
                    rsum[mf][0] += ex2(acc[mf][j][0] * EC) + ex2(acc[mf][j][1] * EC);
                    rsum[mf][1] += ex2(acc[mf][j][2] * EC) + ex2(acc[mf][j][3] * EC);
                }
        }
    }

    // ---- transition: issue pass-B stages 0,1 while reducing ----
    __syncthreads();       // everyone done with pass-A stages
    load_tile64(sb + stage_off(0), kgb, tid);
    load_tile64(sb + stage_off(0) + V_IN_STAGE, vgb, tid);
    CP_COMMIT();
    load_tile64(sb + stage_off(1), kgb + (long long)KT * Dc, tid);
    load_tile64(sb + stage_off(1) + V_IN_STAGE, vgb + (long long)KT * Dc, tid);
    CP_COMMIT();

    float inv[2][2];
    #pragma unroll
    for (int mf = 0; mf < 2; mf++)
        #pragma unroll
        for (int h = 0; h < 2; h++) {
            float s = rsum[mf][h];
            s += __shfl_xor_sync(0xffffffffu, s, 1);
            s += __shfl_xor_sync(0xffffffffu, s, 2);
            inv[mf][h] = 1.f / s;
        }

    // =================== pass B: scores + context ===================
    float cc[2][8][4];
    #pragma unroll
    for (int mf = 0; mf < 2; mf++)
        #pragma unroll
        for (int nf = 0; nf < 8; nf++)
            cc[mf][nf][0] = cc[mf][nf][1] = cc[mf][nf][2] = cc[mf][nf][3] = 0.f;

    for (int kt = 0; kt < NKT; kt++) {
        CP_WAIT1();
        __syncthreads();
        if (kt + 2 < NKT) {
            load_tile64(sb + stage_off(kt + 2), kgb + (long long)(kt + 2) * KT * Dc, tid);
            load_tile64(sb + stage_off(kt + 2) + V_IN_STAGE,
                        vgb + (long long)(kt + 2) * KT * Dc, tid);
        }
        CP_COMMIT();

        const uint32_t kbase = sb + stage_off(kt) + krow;
        const uint32_t vbase = sb + stage_off(kt) + V_IN_STAGE + vrow;

        #pragma unroll
        for (int nb = 0; nb < 4; nb++) {   // 16 S-columns per chunk
            float acc[2][2][4];
            #pragma unroll
            for (int mf = 0; mf < 2; mf++)
                #pragma unroll
                for (int j = 0; j < 2; j++)
                    acc[mf][j][0] = acc[mf][j][1] = acc[mf][j][2] = acc[mf][j][3] = 0.f;
            #pragma unroll
            for (int kk = 0; kk < 4; kk++) {
                uint32_t B[4];
                ldsm4(B, kbase + (uint32_t)(nb * 2048) + (((uint32_t)(kk * 32) + kfr) ^ xr));
                #pragma unroll
                for (int mf = 0; mf < 2; mf++) {
                    mma16816(acc[mf][0], qf[kk][mf], B[0], B[1]);
                    mma16816(acc[mf][1], qf[kk][mf], B[2], B[3]);
                }
            }

            // exp + normalize + stream scores + pack P
            uint32_t pa[2][4];
            #pragma unroll
            for (int mf = 0; mf < 2; mf++) {
                const int r0 = rs + mf * 16 + g, r1 = r0 + 8;
                #pragma unroll
                for (int j = 0; j < 2; j++) {
                    float p0 = ex2(acc[mf][j][0] * EC) * inv[mf][0];
                    float p1 = ex2(acc[mf][j][1] * EC) * inv[mf][0];
                    float p2 = ex2(acc[mf][j][2] * EC) * inv[mf][1];
                    float p3 = ex2(acc[mf][j][3] * EC) * inv[mf][1];
                    int colG = kt * KT + (2 * nb + j) * 8 + 2 * m;
                    __stcs(reinterpret_cast<float2*>(score + (long long)r0 * Sc + colG),
                           make_float2(p0, p1));
                    __stcs(reinterpret_cast<float2*>(score + (long long)r1 * Sc + colG),
                           make_float2(p2, p3));
                    pa[mf][2 * j]     = h2u(__floats2half2_rn(p0, p1));
                    pa[mf][2 * j + 1] = h2u(__floats2half2_rn(p2, p3));
                }
            }

            // PV for this 16-seq chunk
            const uint32_t vb = vbase + (uint32_t)(nb * 2048);
            #pragma unroll
            for (int db = 0; db < 4; db++) {
                uint32_t B[4];
                ldsm4t(B, vb + ((vc0 + (uint32_t)(db * 32)) ^ xr));
                #pragma unroll
                for (int mf = 0; mf < 2; mf++) {
                    mma16816(cc[mf][2 * db],     pa[mf], B[0], B[1]);
                    mma16816(cc[mf][2 * db + 1], pa[mf], B[2], B[3]);
                }
            }
        }
    }

    // ---- write context ----
    #pragma unroll
    for (int mf = 0; mf < 2; mf++) {
        const int r0 = rs + mf * 16 + g, r1 = r0 + 8;
        #pragma unroll
        for (int nf = 0; nf < 8; nf++) {
            int colG = nf * 8 + 2 * m;
            __stcs(reinterpret_cast<float2*>(ctx + (long long)r0 * Dc + colG),
                   make_float2(cc[mf][nf][0], cc[mf][nf][1]));
            __stcs(reinterpret_cast<float2*>(ctx + (long long)r1 * Dc + colG),
                   make_float2(cc[mf][nf][2], cc[mf][nf][3]));
        }
    }
}

extern "C" void kernel_launch(void* const* d_in, const int* in_sizes, int n_in,
                              void* d_out, int out_size) {
    (void)in_sizes; (void)n_in; (void)out_size;
    const float4* q = (const float4*)d_in[0];
    const float4* k = (const float4*)d_in[1];
    const float4* v = (const float4*)d_in[2];
    float* out = (float*)d_out;

    cvt_kernel<<<(3 * N4 + 255) / 256, 256>>>(q, k, v);

    cudaFuncSetAttribute(sdpa_kernel,
                         cudaFuncAttributeMaxDynamicSharedMemorySize, SMEM_TOTAL);
    dim3 grid(Sc / QT, Bc * Hc);  // 8 x 96
    sdpa_kernel<<<grid, NT, SMEM_TOTAL>>>(out);
}

// round 10
// speedup vs baseline: 1.1307x; 1.0103x over previous
#include <cuda_runtime.h>
#include <cuda_fp16.h>
#include <cstdint>

// fp16 mma.sync attention. 128 thr/CTA, 4 warps x 32 q-rows, 3 CTAs/SM.
// Pass A: full-tile accumulators (16 indep HMMA chains). Pass B: chunk-pair
// epilogue (32 S-cols, 8 indep chains) to balance ILP vs registers.
// Triple-buffered K(+V) stages via cp.async wait_group 1. Register-resident P.
// K/V pre-converted fp32->fp16 by cvt kernel; Q converted in-kernel prologue.

namespace {
constexpr int Bc = 8, Hc = 12, Sc = 1024, Dc = 64;
constexpr int QT = 128, KT = 64, NKT = Sc / KT;
constexpr long long SCORE_ELEMS = (long long)Bc * Hc * Sc * Sc;
constexpr float EC = 0.18033688011112042f;  // log2(e) / 8
constexpr int NELEM = Bc * Hc * Sc * Dc;
constexpr int N4 = NELEM / 4;
constexpr int NT = 128;

constexpr int OFF_Q = 0;                       // 128x64 half = 16KB
constexpr int OFF_ST = 16384;                  // 3 stages x (K 8KB + V 8KB)
constexpr int STAGE_SZ = 16384, V_IN_STAGE = 8192;
constexpr int SMEM_TOTAL = OFF_ST + 3 * STAGE_SZ;  // 65536

__device__ __forceinline__ uint32_t swz(uint32_t off) { return off ^ ((off >> 3) & 0x70); }
__device__ __forceinline__ uint32_t smem_u32(const void* p) {
    uint32_t a;
    asm("{ .reg .u64 t; cvta.to.shared.u64 t, %1; cvt.u32.u64 %0, t; }" : "=r"(a) : "l"(p));
    return a;
}
__device__ __forceinline__ uint32_t h2u(__half2 h) { return *reinterpret_cast<uint32_t*>(&h); }
__device__ __forceinline__ float ex2(float x) {
    float r;
    asm("ex2.approx.f32 %0, %1;" : "=f"(r) : "f"(x));
    return r;
}
__device__ __forceinline__ void ldsm4(uint32_t r[4], uint32_t a) {
    asm volatile("ldmatrix.sync.aligned.m8n8.x4.shared.b16 {%0,%1,%2,%3}, [%4];"
                 : "=r"(r[0]), "=r"(r[1]), "=r"(r[2]), "=r"(r[3]) : "r"(a));
}
__device__ __forceinline__ void ldsm4t(uint32_t r[4], uint32_t a) {
    asm volatile("ldmatrix.sync.aligned.m8n8.x4.trans.shared.b16 {%0,%1,%2,%3}, [%4];"
                 : "=r"(r[0]), "=r"(r[1]), "=r"(r[2]), "=r"(r[3]) : "r"(a));
}
__device__ __forceinline__ void mma16816(float c[4], const uint32_t a[4],
                                         uint32_t b0, uint32_t b1) {
    asm volatile(
        "mma.sync.aligned.m16n8k16.row.col.f32.f16.f16.f32 "
        "{%0,%1,%2,%3}, {%4,%5,%6,%7}, {%8,%9}, {%0,%1,%2,%3};"
        : "+f"(c[0]), "+f"(c[1]), "+f"(c[2]), "+f"(c[3])
        : "r"(a[0]), "r"(a[1]), "r"(a[2]), "r"(a[3]), "r"(b0), "r"(b1));
}
__device__ __forceinline__ void cpa16(uint32_t d, const void* s) {
    asm volatile("cp.async.cg.shared.global [%0], [%1], 16;" :: "r"(d), "l"(s) : "memory");
}
#define CP_COMMIT() asm volatile("cp.async.commit_group;" ::: "memory")
#define CP_WAIT1()  asm volatile("cp.async.wait_group 1;" ::: "memory")
}  // namespace

__device__ __align__(16) __half g_kh[NELEM];
__device__ __align__(16) __half g_vh[NELEM];

__global__ __launch_bounds__(256)
void cvt_kernel(const float4* __restrict__ k, const float4* __restrict__ v) {
    int i = blockIdx.x * blockDim.x + threadIdx.x;
    const float4* src;
    uint2* dst;
    int j;
    if (i < N4) { src = k; dst = reinterpret_cast<uint2*>(g_kh); j = i; }
    else        { src = v; dst = reinterpret_cast<uint2*>(g_vh); j = i - N4; }
    float4 x = src[j];
    dst[j] = make_uint2(h2u(__floats2half2_rn(x.x, x.y)), h2u(__floats2half2_rn(x.z, x.w)));
}

namespace {
__device__ __forceinline__ void load_tile64(uint32_t dstBase, const __half* gsrc, int tid) {
    #pragma unroll
    for (int i = 0; i < 4; i++) {
        int c = tid + i * NT;
        int r = c >> 3, ch = c & 7;
        cpa16(dstBase + swz((uint32_t)(r * 128 + ch * 16)), gsrc + r * 64 + ch * 8);
    }
}
__device__ __forceinline__ uint32_t stage_off(int kt) {
    return (uint32_t)(OFF_ST + (kt % 3) * STAGE_SZ);
}
}  // namespace

__global__ __launch_bounds__(NT, 3)
void sdpa_kernel(const float* __restrict__ q, float* __restrict__ out) {
    extern __shared__ char smem[];
    const uint32_t sb = smem_u32(smem);
    const int tid = threadIdx.x, lane = tid & 31, wid = tid >> 5;
    const int g = lane >> 2, m = lane & 3;
    const int rs = wid * 32;
    const uint32_t xr = (uint32_t)((lane & 7) << 4);

    const int bh = blockIdx.y, qb = blockIdx.x;
    const float* qg   = q + ((long long)bh * Sc + qb * QT) * Dc;
    const __half* kgb = g_kh + (long long)bh * Sc * Dc;
    const __half* vgb = g_vh + (long long)bh * Sc * Dc;
    float* score = out + (long long)bh * Sc * Sc + (long long)(qb * QT) * Sc;
    float* ctx   = out + SCORE_ELEMS + ((long long)bh * Sc + qb * QT) * Dc;

    // ---- prologue: async K(0), K(1); convert Q fp32->fp16 meanwhile ----
    load_tile64(sb + stage_off(0), kgb, tid);
    CP_COMMIT();
    load_tile64(sb + stage_off(1), kgb + (long long)KT * Dc, tid);
    CP_COMMIT();
    #pragma unroll
    for (int i0 = 0; i0 < 16; i0++) {
        int i = tid + i0 * NT;
        int r = i >> 4, c4 = (i & 15) << 2;
        float4 x = *reinterpret_cast<const float4*>(qg + r * Dc + c4);
        *reinterpret_cast<uint2*>(smem + OFF_Q + swz((uint32_t)(r * 128 + c4 * 2))) =
            make_uint2(h2u(__floats2half2_rn(x.x, x.y)), h2u(__floats2half2_rn(x.z, x.w)));
    }
    CP_WAIT1();            // K0 landed
    __syncthreads();       // Q visible

    // Q fragments in registers: [kk][mf][4]
    uint32_t qf[4][2][4];
    #pragma unroll
    for (int mf = 0; mf < 2; mf++) {
        uint32_t aq = sb + OFF_Q + (uint32_t)((rs + mf * 16 + (lane & 15)) * 128);
        #pragma unroll
        for (int kk = 0; kk < 4; kk++)
            ldsm4(qf[kk][mf], aq + (((uint32_t)(kk * 32 + ((lane >> 4) * 16))) ^ xr));
    }

    const uint32_t krow = (uint32_t)((((lane >> 4) << 3) + (lane & 7)) * 128);
    const uint32_t vrow = (uint32_t)((lane & 15) * 128);
    const uint32_t vc0 = (uint32_t)((lane >> 4) * 16);
    const uint32_t kfr = (uint32_t)(((lane >> 3) & 1) * 16);

    // =================== pass A: row sums (full-tile ILP) ===================
    float rsum[2][2] = {{0.f, 0.f}, {0.f, 0.f}};
    for (int kt = 0; kt < NKT; kt++) {
        CP_WAIT1();
        __syncthreads();
        if (kt + 2 < NKT)
            load_tile64(sb + stage_off(kt + 2), kgb + (long long)(kt + 2) * KT * Dc, tid);
        CP_COMMIT();

        const uint32_t kbase = sb + stage_off(kt) + krow;
        float acc[2][8][4];
        #pragma unroll
        for (int mf = 0; mf < 2; mf++)
            #pragma unroll
            for (int nf = 0; nf < 8; nf++)
                acc[mf][nf][0] = acc[mf][nf][1] = acc[mf][nf][2] = acc[mf][nf][3] = 0.f;
        #pragma unroll
        for (int kk = 0; kk < 4; kk++) {
            uint32_t kb = (((uint32_t)(kk * 32)) + kfr) ^ xr;
            #pragma unroll
            for (int nb = 0; nb < 4; nb++) {
                uint32_t B[4];
                ldsm4(B, kbase + (uint32_t)(nb * 2048) + kb);
                #pragma unroll
                for (int mf = 0; mf < 2; mf++) {
                    mma16816(acc[mf][2 * nb],     qf[kk][mf], B[0], B[1]);
                    mma16816(acc[mf][2 * nb + 1], qf[kk][mf], B[2], B[3]);
                }
            }
        }
        #pragma unroll
        for (int mf = 0; mf < 2; mf++)
            #pragma unroll
            for (int nf = 0; nf < 8; nf++) {
                rsum[mf][0] += ex2(acc[mf][nf][0] * EC) + ex2(acc[mf][nf][1] * EC);
                rsum[mf][1] += ex2(acc[mf][nf][2] * EC) + ex2(acc[mf][nf][3] * EC);
            }
    }

    // ---- transition: issue pass-B stages 0,1 while reducing ----
    __syncthreads();
    load_tile64(sb + stage_off(0), kgb, tid);
    load_tile64(sb + stage_off(0) + V_IN_STAGE, vgb, tid);
    CP_COMMIT();
    load_tile64(sb + stage_off(1), kgb + (long long)KT * Dc, tid);
    load_tile64(sb + stage_off(1) + V_IN_STAGE, vgb + (long long)KT * Dc, tid);
    CP_COMMIT();

    float inv[2][2];
    #pragma unroll
    for (int mf = 0; mf < 2; mf++)
        #pragma unroll
        for (int h = 0; h < 2; h++) {
            float s = rsum[mf][h];
            s += __shfl_xor_sync(0xffffffffu, s, 1);
            s += __shfl_xor_sync(0xffffffffu, s, 2);
            inv[mf][h] = 1.f / s;
        }

    // =================== pass B: scores + context (chunk pairs) ===================
    float cc[2][8][4];
    #pragma unroll
    for (int mf = 0; mf < 2; mf++)
        #pragma unroll
        for (int nf = 0; nf < 8; nf++)
            cc[mf][nf][0] = cc[mf][nf][1] = cc[mf][nf][2] = cc[mf][nf][3] = 0.f;

    for (int kt = 0; kt < NKT; kt++) {
        CP_WAIT1();
        __syncthreads();
        if (kt + 2 < NKT) {
            load_tile64(sb + stage_off(kt + 2), kgb + (long long)(kt + 2) * KT * Dc, tid);
            load_tile64(sb + stage_off(kt + 2) + V_IN_STAGE,
                        vgb + (long long)(kt + 2) * KT * Dc, tid);
        }
        CP_COMMIT();

        const uint32_t kbase = sb + stage_off(kt) + krow;
        const uint32_t vbase = sb + stage_off(kt) + V_IN_STAGE + vrow;

        #pragma unroll
        for (int nb2 = 0; nb2 < 2; nb2++) {   // 32 S-columns per chunk pair
            float acc[2][2][2][4];            // [mf][c][j][4] -> 8 indep chains
            #pragma unroll
            for (int mf = 0; mf < 2; mf++)
                #pragma unroll
                for (int c = 0; c < 2; c++)
                    #pragma unroll
                    for (int j = 0; j < 2; j++)
                        acc[mf][c][j][0] = acc[mf][c][j][1] =
                        acc[mf][c][j][2] = acc[mf][c][j][3] = 0.f;
            #pragma unroll
            for (int kk = 0; kk < 4; kk++) {
                uint32_t kb = (((uint32_t)(kk * 32)) + kfr) ^ xr;
                #pragma unroll
                for (int c = 0; c < 2; c++) {
                    uint32_t B[4];
                    ldsm4(B, kbase + (uint32_t)((2 * nb2 + c) * 2048) + kb);
                    #pragma unroll
                    for (int mf = 0; mf < 2; mf++) {
                        mma16816(acc[mf][c][0], qf[kk][mf], B[0], B[1]);
                        mma16816(acc[mf][c][1], qf[kk][mf], B[2], B[3]);
                    }
                }
            }

            // exp + normalize + stream scores + pack P
            uint32_t pa[2][2][4];
            #pragma unroll
            for (int mf = 0; mf < 2; mf++) {
                const int r0 = rs + mf * 16 + g, r1 = r0 + 8;
                #pragma unroll
                for (int c = 0; c < 2; c++) {
                    #pragma unroll
                    for (int j = 0; j < 2; j++) {
                        float p0 = ex2(acc[mf][c][j][0] * EC) * inv[mf][0];
                        float p1 = ex2(acc[mf][c][j][1] * EC) * inv[mf][0];
                        float p2 = ex2(acc[mf][c][j][2] * EC) * inv[mf][1];
                        float p3 = ex2(acc[mf][c][j][3] * EC) * inv[mf][1];
                        int colG = kt * KT + (2 * nb2 + c) * 16 + j * 8 + 2 * m;
                        __stcs(reinterpret_cast<float2*>(score + (long long)r0 * Sc + colG),
                               make_float2(p0, p1));
                        __stcs(reinterpret_cast<float2*>(score + (long long)r1 * Sc + colG),
                               make_float2(p2, p3));
                        pa[mf][c][2 * j]     = h2u(__floats2half2_rn(p0, p1));
                        pa[mf][c][2 * j + 1] = h2u(__floats2half2_rn(p2, p3));
                    }
                }
            }

            // PV for this 32-seq chunk pair
            #pragma unroll
            for (int db = 0; db < 4; db++) {
                uint32_t B0[4], B1[4];
                uint32_t vo = (vc0 + (uint32_t)(db * 32)) ^ xr;
                ldsm4t(B0, vbase + (uint32_t)((2 * nb2) * 2048) + vo);
                ldsm4t(B1, vbase + (uint32_t)((2 * nb2 + 1) * 2048) + vo);
                #pragma unroll
                for (int mf = 0; mf < 2; mf++) {
                    mma16816(cc[mf][2 * db],     pa[mf][0], B0[0], B0[1]);
                    mma16816(cc[mf][2 * db + 1], pa[mf][0], B0[2], B0[3]);
                    mma16816(cc[mf][2 * db],     pa[mf][1], B1[0], B1[1]);
                    mma16816(cc[mf][2 * db + 1], pa[mf][1], B1[2], B1[3]);
                }
            }
        }
    }

    // ---- write context ----
    #pragma unroll
    for (int mf = 0; mf < 2; mf++) {
        const int r0 = rs + mf * 16 + g, r1 = r0 + 8;
        #pragma unroll
        for (int nf = 0; nf < 8; nf++) {
            int colG = nf * 8 + 2 * m;
            __stcs(reinterpret_cast<float2*>(ctx + (long long)r0 * Dc + colG),
                   make_float2(cc[mf][nf][0], cc[mf][nf][1]));
            __stcs(reinterpret_cast<float2*>(ctx + (long long)r1 * Dc + colG),
                   make_float2(cc[mf][nf][2], cc[mf][nf][3]));
        }
    }
}

extern "C" void kernel_launch(void* const* d_in, const int* in_sizes, int n_in,
                              void* d_out, int out_size) {
    (void)in_sizes; (void)n_in; (void)out_size;
    const float* q = (const float*)d_in[0];
    const float4* k = (const float4*)d_in[1];
    const float4* v = (const float4*)d_in[2];
    float* out = (float*)d_out;

    cvt_kernel<<<(2 * N4 + 255) / 256, 256>>>(k, v);

    cudaFuncSetAttribute(sdpa_kernel,
                         cudaFuncAttributeMaxDynamicSharedMemorySize, SMEM_TOTAL);
    dim3 grid(Sc / QT, Bc * Hc);  // 8 x 96
    sdpa_kernel<<<grid, NT, SMEM_TOTAL>>>(q, out);
}